// round 15
// baseline (speedup 1.0000x reference)
#include <cuda_runtime.h>
#include <cstdint>

#define SLEN    2048
#define DHEAD   64
#define BHN     64
#define TQ      256
#define TK      64
#define NTHREADS 512
#define NKT     (SLEN / TK)
#define OUT_ELEMS ((size_t)BHN * SLEN * DHEAD)   // 8,388,608

#define PITCHK  288                     // K & VT pitch bytes (72 words)
#define PITCHS  272                     // V stage pitch bytes
#define KBUF    (64 * PITCHK)           // 18432
#define VSBUF   (64 * PITCHS)           // 17408

// ---- dynamic smem layout (bytes) ----
#define OFF_K0  0
#define OFF_K1  18432
#define OFF_VS  36864
#define OFF_VT  54272
#define OFF_BM  72704                   // 256 rows x 68 words = 69632 B
#define OFF_RS  142336                  // 256 floats
#define SMEM_BYTES (OFF_RS + 1024)      // 143360 -> 1 CTA/SM (16 warps)
#define BM_STRIDE 68

static __device__ __forceinline__ uint32_t smem_u32(const void* p) {
    uint32_t a;
    asm("{ .reg .u64 t; cvta.to.shared.u64 t, %1; cvt.u32.u64 %0, t; }" : "=r"(a) : "l"(p));
    return a;
}
static __device__ __forceinline__ void cp16(uint32_t sm, const void* g) {
    asm volatile("cp.async.cg.shared.global [%0], [%1], 16;" :: "r"(sm), "l"(g));
}
static __device__ __forceinline__ uint32_t f2tf(float f) {
    uint32_t u;
    asm("cvt.rna.tf32.f32 %0, %1;" : "=r"(u) : "f"(f));
    return u;
}
static __device__ __forceinline__ void mma_tf32(float* c, const uint32_t* a,
                                                uint32_t b0, uint32_t b1) {
    asm volatile("mma.sync.aligned.m16n8k8.row.col.f32.tf32.tf32.f32 "
                 "{%0,%1,%2,%3}, {%4,%5,%6,%7}, {%8,%9}, {%0,%1,%2,%3};"
                 : "+f"(c[0]), "+f"(c[1]), "+f"(c[2]), "+f"(c[3])
                 : "r"(a[0]), "r"(a[1]), "r"(a[2]), "r"(a[3]), "r"(b0), "r"(b1));
}
static __device__ __forceinline__ void lds64(uint32_t& a, uint32_t& b, uint32_t addr) {
    asm volatile("ld.shared.v2.b32 {%0,%1}, [%2];" : "=r"(a), "=r"(b) : "r"(addr));
}

__global__ void __launch_bounds__(NTHREADS, 1)
sdpa_tf32_kernel(const float* __restrict__ Qg_all,
                 const float* __restrict__ Kg_all,
                 const float* __restrict__ Vg_all,
                 const int*   __restrict__ Mg_all,
                 float* __restrict__ Og_all,
                 float* __restrict__ Ag_all)
{
    extern __shared__ uint8_t smem[];
    const uint32_t smb = smem_u32(smem);
    uint32_t* BMw = (uint32_t*)(smem + OFF_BM);
    float* rowsum = (float*)(smem + OFF_RS);

    const int tid = threadIdx.x;
    const int w   = tid >> 5;
    const int l   = tid & 31;
    const int bh  = blockIdx.y;
    const int q0  = blockIdx.x * TQ;

    const float* Qg = Qg_all + (size_t)bh * SLEN * DHEAD;
    const float* Kg = Kg_all + (size_t)bh * SLEN * DHEAD;
    const float* Vg = Vg_all + (size_t)bh * SLEN * DHEAD;
    const int*   Mg = Mg_all + (size_t)bh * SLEN * SLEN;
    float*       Og = Og_all + (size_t)bh * SLEN * DHEAD;
    float*       Ag = Ag_all + (size_t)bh * SLEN * SLEN;

    auto issue_k = [&](int kt, int b) {
        if (kt < NKT) {
            const float* Kt = Kg + (size_t)kt * TK * DHEAD;
            const uint32_t base = smb + OFF_K0 + b * KBUF;
#pragma unroll
            for (int j = 0; j < 2; ++j) {
                const int idx = tid + j * NTHREADS;       // 0..1023
                const int row = idx >> 4, ch = idx & 15;
                cp16(base + row * PITCHK + ch * 16, Kt + row * DHEAD + ch * 4);
            }
        }
        asm volatile("cp.async.commit_group;" ::: "memory");
    };
    auto issue_v = [&](int kt) {
        if (kt < NKT) {
            const float* Vt = Vg + (size_t)kt * TK * DHEAD;
            const uint32_t base = smb + OFF_VS;
#pragma unroll
            for (int j = 0; j < 2; ++j) {
                const int idx = tid + j * NTHREADS;
                const int row = idx >> 4, ch = idx & 15;
                cp16(base + row * PITCHS + ch * 16, Vt + row * DHEAD + ch * 4);
            }
        }
        asm volatile("cp.async.commit_group;" ::: "memory");
    };
    // K stage: in-place RNA tf32 (1152 float4)
    auto sweep_k = [&](int b) {
        const uint32_t a0 = smb + OFF_K0 + b * KBUF;
#pragma unroll
        for (int j = 0; j < 3; ++j) {
            const int idx = tid + j * NTHREADS;
            if (idx < 1152) {
                const uint32_t ad = a0 + idx * 16;
                uint32_t x, y, z, t;
                asm volatile("ld.shared.v4.b32 {%0,%1,%2,%3}, [%4];"
                             : "=r"(x), "=r"(y), "=r"(z), "=r"(t) : "r"(ad));
                x = f2tf(__uint_as_float(x)); y = f2tf(__uint_as_float(y));
                z = f2tf(__uint_as_float(z)); t = f2tf(__uint_as_float(t));
                asm volatile("st.shared.v4.b32 [%0], {%1,%2,%3,%4};"
                             :: "r"(ad), "r"(x), "r"(y), "r"(z), "r"(t));
            }
        }
    };
    // VS [k][d] -> VT [d][k] with f2tf (1024 chunks)
    auto transpose_v = [&]() {
#pragma unroll
        for (int j = 0; j < 2; ++j) {
            const int idx = tid + j * NTHREADS;
            const int k = idx & 63, dc = idx >> 6;       // dc 0..15
            const uint32_t sa = smb + OFF_VS + k * PITCHS + dc * 16;
            uint32_t x, y, z, t;
            asm volatile("ld.shared.v4.b32 {%0,%1,%2,%3}, [%4];"
                         : "=r"(x), "=r"(y), "=r"(z), "=r"(t) : "r"(sa));
            x = f2tf(__uint_as_float(x)); y = f2tf(__uint_as_float(y));
            z = f2tf(__uint_as_float(z)); t = f2tf(__uint_as_float(t));
            const uint32_t da = smb + OFF_VT + (dc * 4) * PITCHK + k * 4;
            asm volatile("st.shared.b32 [%0], %1;" :: "r"(da),              "r"(x));
            asm volatile("st.shared.b32 [%0], %1;" :: "r"(da + PITCHK),     "r"(y));
            asm volatile("st.shared.b32 [%0], %1;" :: "r"(da + 2 * PITCHK), "r"(z));
            asm volatile("st.shared.b32 [%0], %1;" :: "r"(da + 3 * PITCHK), "r"(t));
        }
    };

    // prologue: V(0), K(0), K(1)
    issue_v(0);
    issue_k(0, 0);
    issue_k(1, 1);

    // ================= bit-packed mask: 256 rows x 2048 bits =================
    // 16384 words; 16 warps x 8 words per iteration.
    for (int base = 0; base < 16384; base += 128) {
        const int w0idx = base + w * 8;
        int vals[8];
#pragma unroll
        for (int j = 0; j < 8; ++j) {
            const int widx = w0idx + j;
            vals[j] = Mg[(size_t)(q0 + (widx >> 6)) * SLEN + (widx & 63) * 32 + l];
        }
#pragma unroll
        for (int j = 0; j < 8; ++j) {
            const unsigned bal = __ballot_sync(0xffffffffu, vals[j] != 0);
            const int widx = w0idx + j;
            if (l == 0) BMw[(widx >> 6) * BM_STRIDE + (widx & 63)] = bal;
        }
    }

    // ---- Q A-fragments (tf32, relabeled kpos: p -> d = 2p / 2(p-4)+1) ----
    const int rl0 = w * 16 + (l >> 2);          // 0..255
    const int r0  = q0 + rl0;
    uint32_t qa[8][4];
    {
        const float* Qr0 = Qg + (size_t)r0 * DHEAD;
#pragma unroll
        for (int s = 0; s < 8; ++s) {
            const int d0 = s * 8 + (l & 3) * 2;
            qa[s][0] = f2tf(Qr0[d0]);
            qa[s][1] = f2tf(Qr0[8 * DHEAD + d0]);
            qa[s][2] = f2tf(Qr0[d0 + 1]);
            qa[s][3] = f2tf(Qr0[8 * DHEAD + d0 + 1]);
        }
    }

    // per-lane base offset (same formula for K and VT tiles)
    const uint32_t laneB = (uint32_t)((l >> 2) * PITCHK + (l & 3) * 8);
    const int j0 = (l & 3) * 2;

    float oacc[8][4];
#pragma unroll
    for (int nb = 0; nb < 8; ++nb) { oacc[nb][0]=0.f; oacc[nb][1]=0.f; oacc[nb][2]=0.f; oacc[nb][3]=0.f; }
    float rs0 = 0.f, rs1 = 0.f;

    // ============================ PASS 1: rowsums + O ============================
    for (int kt = 0; kt < NKT; ++kt) {
        const int b = kt & 1;

        asm volatile("cp.async.wait_group 1;" ::: "memory");   // K(kt), V(kt) ready
        __syncthreads();

        transpose_v();        // VS -> VT (tf32)
        sweep_k(b);           // K stage -> tf32 in place
        __syncthreads();

        issue_v(kt + 1);      // VS free now

        // ---- S = Q K^T (LDS.64 B-frags, conflict-free) ----
        float sacc[8][4];
#pragma unroll
        for (int nb = 0; nb < 8; ++nb) { sacc[nb][0]=0.f; sacc[nb][1]=0.f; sacc[nb][2]=0.f; sacc[nb][3]=0.f; }
        const uint32_t aK = smb + OFF_K0 + b * KBUF + laneB;
#pragma unroll
        for (int s = 0; s < 8; ++s) {
#pragma unroll
            for (int nb = 0; nb < 8; ++nb) {
                uint32_t b0, b1;
                lds64(b0, b1, aK + nb * (8 * PITCHK) + s * 32);
                mma_tf32(sacc[nb], qa[s], b0, b1);
            }
        }

        // ---- mask bits, exp, rowsum, P->A frags ({c0,c2,c1,c3}) ----
        uint64_t bits0, bits1;
        {
            uint2 b0v = *(const uint2*)(BMw + rl0 * BM_STRIDE + kt * 2);
            uint2 b1v = *(const uint2*)(BMw + (rl0 + 8) * BM_STRIDE + kt * 2);
            bits0 = ((uint64_t)b0v.y << 32 | b0v.x) >> j0;
            bits1 = ((uint64_t)b1v.y << 32 | b1v.x) >> j0;
        }
        uint32_t pp[8][4];
#pragma unroll
        for (int nb = 0; nb < 8; ++nb) {
            const uint32_t s0 = (uint32_t)(bits0 >> (nb * 8));
            const uint32_t s1 = (uint32_t)(bits1 >> (nb * 8));
            float p0 = (s0 & 1) ? __expf(sacc[nb][0] * 0.125f) : 0.f;
            float p1 = (s0 & 2) ? __expf(sacc[nb][1] * 0.125f) : 0.f;
            float p2 = (s1 & 1) ? __expf(sacc[nb][2] * 0.125f) : 0.f;
            float p3 = (s1 & 2) ? __expf(sacc[nb][3] * 0.125f) : 0.f;
            rs0 += p0 + p1;
            rs1 += p2 + p3;
            pp[nb][0] = f2tf(p0);
            pp[nb][1] = f2tf(p2);
            pp[nb][2] = f2tf(p1);
            pp[nb][3] = f2tf(p3);
        }

        // ---- O += P V  (VT natural layout, LDS.64 B-frags) ----
        const uint32_t aV = smb + OFF_VT + laneB;
#pragma unroll
        for (int s = 0; s < 8; ++s) {
#pragma unroll
            for (int nb = 0; nb < 8; ++nb) {
                uint32_t b0, b1;
                lds64(b0, b1, aV + nb * (8 * PITCHK) + s * 32);
                mma_tf32(oacc[nb], pp[s], b0, b1);
            }
        }

        __syncthreads();
        issue_k(kt + 2, b);
    }
    asm volatile("cp.async.wait_group 0;" ::: "memory");   // drain

    // ---- row sums: reduce 4 lanes per row, invert ----
    rs0 += __shfl_xor_sync(0xffffffffu, rs0, 1);
    rs0 += __shfl_xor_sync(0xffffffffu, rs0, 2);
    rs1 += __shfl_xor_sync(0xffffffffu, rs1, 1);
    rs1 += __shfl_xor_sync(0xffffffffu, rs1, 2);
    if ((l & 3) == 0) {
        rowsum[rl0]     = rs0;
        rowsum[rl0 + 8] = rs1;
    }
    __syncthreads();
    if (tid < TQ) rowsum[tid] = 1.0f / rowsum[tid];
    __syncthreads();

    const float inv0 = rowsum[rl0];
    const float inv1 = rowsum[rl0 + 8];

    // ---- write normalized O ----
    {
        float* or0 = Og + (size_t)r0 * DHEAD + (l & 3) * 2;
        float* or8 = or0 + 8 * DHEAD;
#pragma unroll
        for (int nb = 0; nb < 8; ++nb) {
            *(float2*)(or0 + nb * 8) = make_float2(oacc[nb][0] * inv0, oacc[nb][1] * inv0);
            *(float2*)(or8 + nb * 8) = make_float2(oacc[nb][2] * inv1, oacc[nb][3] * inv1);
        }
    }
    __syncthreads();

    // ============================ PASS 2: normalized attention ============================
    issue_k(0, 0);
    issue_k(1, 1);

    float* ab0 = Ag + (size_t)r0 * SLEN + (l & 3) * 2;

    for (int kt = 0; kt < NKT; ++kt) {
        const int b = kt & 1;

        asm volatile("cp.async.wait_group 1;" ::: "memory");
        __syncthreads();
        sweep_k(b);
        __syncthreads();

        // ---- S recompute (LDS.64) ----
        float sacc[8][4];
#pragma unroll
        for (int nb = 0; nb < 8; ++nb) { sacc[nb][0]=0.f; sacc[nb][1]=0.f; sacc[nb][2]=0.f; sacc[nb][3]=0.f; }
        const uint32_t aK = smb + OFF_K0 + b * KBUF + laneB;
#pragma unroll
        for (int s = 0; s < 8; ++s) {
#pragma unroll
            for (int nb = 0; nb < 8; ++nb) {
                uint32_t b0, b1;
                lds64(b0, b1, aK + nb * (8 * PITCHK) + s * 32);
                mma_tf32(sacc[nb], qa[s], b0, b1);
            }
        }

        // ---- exp * inv, write normalized attention once ----
        uint64_t bits0, bits1;
        {
            uint2 b0v = *(const uint2*)(BMw + rl0 * BM_STRIDE + kt * 2);
            uint2 b1v = *(const uint2*)(BMw + (rl0 + 8) * BM_STRIDE + kt * 2);
            bits0 = ((uint64_t)b0v.y << 32 | b0v.x) >> j0;
            bits1 = ((uint64_t)b1v.y << 32 | b1v.x) >> j0;
        }
        float* ar0 = ab0 + kt * TK;
        float* ar8 = ar0 + 8 * SLEN;
#pragma unroll
        for (int nb = 0; nb < 8; ++nb) {
            const uint32_t s0 = (uint32_t)(bits0 >> (nb * 8));
            const uint32_t s1 = (uint32_t)(bits1 >> (nb * 8));
            float p0 = (s0 & 1) ? __expf(sacc[nb][0] * 0.125f) * inv0 : 0.f;
            float p1 = (s0 & 2) ? __expf(sacc[nb][1] * 0.125f) * inv0 : 0.f;
            float p2 = (s1 & 1) ? __expf(sacc[nb][2] * 0.125f) * inv1 : 0.f;
            float p3 = (s1 & 2) ? __expf(sacc[nb][3] * 0.125f) * inv1 : 0.f;
            *(float2*)(ar0 + nb * 8) = make_float2(p0, p1);
            *(float2*)(ar8 + nb * 8) = make_float2(p2, p3);
        }

        __syncthreads();
        issue_k(kt + 2, b);
    }
}

extern "C" void kernel_launch(void* const* d_in, const int* in_sizes, int n_in,
                              void* d_out, int out_size)
{
    const float* Q    = (const float*)d_in[0];
    const float* K    = (const float*)d_in[1];
    const float* V    = (const float*)d_in[2];
    const int*   mask = (const int*)d_in[3];
    (void)in_sizes; (void)n_in; (void)out_size;

    float* out  = (float*)d_out;
    float* attn = out + OUT_ELEMS;

    static int configured = 0;
    if (!configured) {
        cudaFuncSetAttribute(sdpa_tf32_kernel,
                             cudaFuncAttributeMaxDynamicSharedMemorySize, SMEM_BYTES);
        configured = 1;
    }

    dim3 grid(SLEN / TQ, BHN);   // (8, 64)
    sdpa_tf32_kernel<<<grid, NTHREADS, SMEM_BYTES>>>(Q, K, V, mask, out, attn);
}

// round 16
// speedup vs baseline: 1.3182x; 1.3182x over previous
#include <cuda_runtime.h>
#include <cuda_fp16.h>
#include <cstdint>

#define SLEN    2048
#define DHEAD   64
#define BHN     64
#define TQ      128
#define TK      64
#define NTHREADS 256
#define NKT     (SLEN / TK)
#define OUT_ELEMS ((size_t)BHN * SLEN * DHEAD)   // 8,388,608

#define PS      272                     // fp32 stage pitch (bytes per 64-f32 row)
#define PH      160                     // fp16 tile pitch (128 B data + 32 pad)
#define SBUF    (64 * PS)               // 17408
#define HBUF    (64 * PH)               // 10240

// ---- dynamic smem layout (bytes) ----
#define OFF_KS  0
#define OFF_VS  17408
#define OFF_KH  34816
#define OFF_VT  45056
#define OFF_BM  55296                   // 128 rows x 68 words = 34816
#define OFF_RS  90112                   // 128 floats
#define SMEM_BYTES 90624                // -> 2 CTAs/SM
#define BM_STRIDE 68

static __device__ __forceinline__ uint32_t smem_u32(const void* p) {
    uint32_t a;
    asm("{ .reg .u64 t; cvta.to.shared.u64 t, %1; cvt.u32.u64 %0, t; }" : "=r"(a) : "l"(p));
    return a;
}
static __device__ __forceinline__ void cp16(uint32_t sm, const void* g) {
    asm volatile("cp.async.cg.shared.global [%0], [%1], 16;" :: "r"(sm), "l"(g));
}
static __device__ __forceinline__ uint32_t h2pack(float lo, float hi) {
    __half2 h = __floats2half2_rn(lo, hi);
    return *(uint32_t*)&h;
}
static __device__ __forceinline__ void mma_f16(float* c, const uint32_t* a,
                                               uint32_t b0, uint32_t b1) {
    asm volatile("mma.sync.aligned.m16n8k16.row.col.f32.f16.f16.f32 "
                 "{%0,%1,%2,%3}, {%4,%5,%6,%7}, {%8,%9}, {%0,%1,%2,%3};"
                 : "+f"(c[0]), "+f"(c[1]), "+f"(c[2]), "+f"(c[3])
                 : "r"(a[0]), "r"(a[1]), "r"(a[2]), "r"(a[3]), "r"(b0), "r"(b1));
}
static __device__ __forceinline__ void lds64(uint32_t& a, uint32_t& b, uint32_t addr) {
    asm volatile("ld.shared.v2.b32 {%0,%1}, [%2];" : "=r"(a), "=r"(b) : "r"(addr));
}

__global__ void __launch_bounds__(NTHREADS, 2)
sdpa_f16_kernel(const float* __restrict__ Qg_all,
                const float* __restrict__ Kg_all,
                const float* __restrict__ Vg_all,
                const int*   __restrict__ Mg_all,
                float* __restrict__ Og_all,
                float* __restrict__ Ag_all)
{
    extern __shared__ uint8_t smem[];
    const uint32_t smb = smem_u32(smem);
    uint32_t* BMw = (uint32_t*)(smem + OFF_BM);
    float* rowsum = (float*)(smem + OFF_RS);

    const int tid = threadIdx.x;
    const int w   = tid >> 5;
    const int l   = tid & 31;
    const int bh  = blockIdx.y;
    const int q0  = blockIdx.x * TQ;

    const float* Qg = Qg_all + (size_t)bh * SLEN * DHEAD;
    const float* Kg = Kg_all + (size_t)bh * SLEN * DHEAD;
    const float* Vg = Vg_all + (size_t)bh * SLEN * DHEAD;
    const int*   Mg = Mg_all + (size_t)bh * SLEN * SLEN;
    float*       Og = Og_all + (size_t)bh * SLEN * DHEAD;
    float*       Ag = Ag_all + (size_t)bh * SLEN * SLEN;

    // one cp.async group per tile: K (+V in pass 1) raw fp32 into stages
    auto issue_kv = [&](int kt) {
        if (kt < NKT) {
            const float* Kt = Kg + (size_t)kt * TK * DHEAD;
            const float* Vt = Vg + (size_t)kt * TK * DHEAD;
#pragma unroll
            for (int j = 0; j < 4; ++j) {
                const int idx = tid + j * NTHREADS;      // 0..1023
                const int row = idx >> 4, ch = idx & 15;
                cp16(smb + OFF_KS + row * PS + ch * 16, Kt + row * DHEAD + ch * 4);
                cp16(smb + OFF_VS + row * PS + ch * 16, Vt + row * DHEAD + ch * 4);
            }
        }
        asm volatile("cp.async.commit_group;" ::: "memory");
    };
    auto issue_k2 = [&](int kt) {
        if (kt < NKT) {
            const float* Kt = Kg + (size_t)kt * TK * DHEAD;
#pragma unroll
            for (int j = 0; j < 4; ++j) {
                const int idx = tid + j * NTHREADS;
                const int row = idx >> 4, ch = idx & 15;
                cp16(smb + OFF_KS + row * PS + ch * 16, Kt + row * DHEAD + ch * 4);
            }
        }
        asm volatile("cp.async.commit_group;" ::: "memory");
    };
    // KS fp32 -> KH fp16 (natural d order)
    auto convert_k = [&]() {
#pragma unroll
        for (int j = 0; j < 4; ++j) {
            const int idx = tid + j * NTHREADS;
            const int row = idx >> 4, dc = idx & 15;
            float4 v = *(const float4*)(smem + OFF_KS + row * PS + dc * 16);
            uint2 h;
            h.x = h2pack(v.x, v.y);
            h.y = h2pack(v.z, v.w);
            *(uint2*)(smem + OFF_KH + row * PH + dc * 8) = h;
        }
    };
    // VS [k][d] fp32 -> VT [d][pos(k)] fp16, pos = slot permutation for k16 MMA
    auto convert_v = [&]() {
#pragma unroll
        for (int j = 0; j < 4; ++j) {
            const int idx = tid + j * NTHREADS;
            const int k = idx & 63, dc = idx >> 6;       // dc 0..15 -> d = 4dc..4dc+3
            float4 v = *(const float4*)(smem + OFF_VS + k * PS + dc * 16);
            const int q = k & 15, g = k >> 4;
            const int pos = g * 16 + ((q & 6) << 1) + ((q >> 2) & 2) + (q & 1);
            __half h0 = __float2half_rn(v.x);
            __half h1 = __float2half_rn(v.y);
            __half h2 = __float2half_rn(v.z);
            __half h3 = __float2half_rn(v.w);
            uint8_t* base = smem + OFF_VT + pos * 2;
            *(__half*)(base + (dc * 4 + 0) * PH) = h0;
            *(__half*)(base + (dc * 4 + 1) * PH) = h1;
            *(__half*)(base + (dc * 4 + 2) * PH) = h2;
            *(__half*)(base + (dc * 4 + 3) * PH) = h3;
        }
    };

    // prologue
    issue_kv(0);

    // ================= bit-packed mask: 128 rows x 2048 bits =================
    for (int base = 0; base < 8192; base += 64) {
        const int w0idx = base + w * 8;
        int vals[8];
#pragma unroll
        for (int j = 0; j < 8; ++j) {
            const int widx = w0idx + j;
            vals[j] = Mg[(size_t)(q0 + (widx >> 6)) * SLEN + (widx & 63) * 32 + l];
        }
#pragma unroll
        for (int j = 0; j < 8; ++j) {
            const unsigned bal = __ballot_sync(0xffffffffu, vals[j] != 0);
            const int widx = w0idx + j;
            if (l == 0) BMw[(widx >> 6) * BM_STRIDE + (widx & 63)] = bal;
        }
    }

    // ---- Q A-fragments (fp16, m16n8k16 layout; d0 = 16j + 4(l&3)) ----
    const int rl0 = w * 16 + (l >> 2);
    const int r0  = q0 + rl0;
    uint32_t qa[4][4];
    {
        const float* Qr0 = Qg + (size_t)r0 * DHEAD;
        const float* Qr8 = Qr0 + 8 * DHEAD;
#pragma unroll
        for (int j = 0; j < 4; ++j) {
            const int d0 = j * 16 + (l & 3) * 4;
            float4 a = *(const float4*)(Qr0 + d0);
            float4 b = *(const float4*)(Qr8 + d0);
            qa[j][0] = h2pack(a.x, a.y);
            qa[j][1] = h2pack(b.x, b.y);
            qa[j][2] = h2pack(a.z, a.w);
            qa[j][3] = h2pack(b.z, b.w);
        }
    }

    // per-lane B-frag base offset (same formula for KH and VT)
    const uint32_t laneH = (uint32_t)((l >> 2) * PH + (l & 3) * 8);
    const int j0 = (l & 3) * 2;

    float oacc[8][4];
#pragma unroll
    for (int nb = 0; nb < 8; ++nb) { oacc[nb][0]=0.f; oacc[nb][1]=0.f; oacc[nb][2]=0.f; oacc[nb][3]=0.f; }
    float rs0 = 0.f, rs1 = 0.f;

    // ============================ PASS 1: rowsums + O ============================
    for (int kt = 0; kt < NKT; ++kt) {

        asm volatile("cp.async.wait_group 0;" ::: "memory");   // stages = tile kt
        __syncthreads();                                       // all warps done with kt-1 tiles

        convert_v();
        convert_k();
        __syncthreads();

        issue_kv(kt + 1);      // stages free; overlap with compute

        // ---- S = Q K^T (fp16 k16: 32 LDS.64 + 32 MMA) ----
        float sacc[8][4];
#pragma unroll
        for (int nb = 0; nb < 8; ++nb) { sacc[nb][0]=0.f; sacc[nb][1]=0.f; sacc[nb][2]=0.f; sacc[nb][3]=0.f; }
        const uint32_t aKH = smb + OFF_KH + laneH;
#pragma unroll
        for (int j = 0; j < 4; ++j) {
#pragma unroll
            for (int nb = 0; nb < 8; ++nb) {
                uint32_t b0, b1;
                lds64(b0, b1, aKH + nb * (8 * PH) + j * 32);
                mma_f16(sacc[nb], qa[j], b0, b1);
            }
        }

        // ---- mask bits, exp, rowsum, P halves ----
        uint64_t bits0, bits1;
        {
            uint2 b0v = *(const uint2*)(BMw + rl0 * BM_STRIDE + kt * 2);
            uint2 b1v = *(const uint2*)(BMw + (rl0 + 8) * BM_STRIDE + kt * 2);
            bits0 = ((uint64_t)b0v.y << 32 | b0v.x) >> j0;
            bits1 = ((uint64_t)b1v.y << 32 | b1v.x) >> j0;
        }
        uint32_t phx[8], phy[8];
#pragma unroll
        for (int nb = 0; nb < 8; ++nb) {
            const uint32_t s0 = (uint32_t)(bits0 >> (nb * 8));
            const uint32_t s1 = (uint32_t)(bits1 >> (nb * 8));
            float p0 = (s0 & 1) ? __expf(sacc[nb][0] * 0.125f) : 0.f;
            float p1 = (s0 & 2) ? __expf(sacc[nb][1] * 0.125f) : 0.f;
            float p2 = (s1 & 1) ? __expf(sacc[nb][2] * 0.125f) : 0.f;
            float p3 = (s1 & 2) ? __expf(sacc[nb][3] * 0.125f) : 0.f;
            rs0 += p0 + p1;
            rs1 += p2 + p3;
            phx[nb] = h2pack(p0, p1);
            phy[nb] = h2pack(p2, p3);
        }

        // ---- O += P V (VT permuted; A-frag = {phx[2j], phy[2j], phx[2j+1], phy[2j+1]}) ----
        const uint32_t aVT = smb + OFF_VT + laneH;
#pragma unroll
        for (int j = 0; j < 4; ++j) {
            uint32_t A[4] = {phx[2 * j], phy[2 * j], phx[2 * j + 1], phy[2 * j + 1]};
#pragma unroll
            for (int nb = 0; nb < 8; ++nb) {
                uint32_t b0, b1;
                lds64(b0, b1, aVT + nb * (8 * PH) + j * 32);
                mma_f16(oacc[nb], A, b0, b1);
            }
        }
    }
    asm volatile("cp.async.wait_group 0;" ::: "memory");   // drain empty tail group

    // ---- row sums: reduce 4 lanes per row, invert ----
    rs0 += __shfl_xor_sync(0xffffffffu, rs0, 1);
    rs0 += __shfl_xor_sync(0xffffffffu, rs0, 2);
    rs1 += __shfl_xor_sync(0xffffffffu, rs1, 1);
    rs1 += __shfl_xor_sync(0xffffffffu, rs1, 2);
    if ((l & 3) == 0) {
        rowsum[rl0]     = rs0;
        rowsum[rl0 + 8] = rs1;
    }
    __syncthreads();
    if (tid < TQ) rowsum[tid] = 1.0f / rowsum[tid];
    __syncthreads();

    const float inv0 = rowsum[rl0];
    const float inv1 = rowsum[rl0 + 8];

    // ---- write normalized O ----
    {
        float* or0 = Og + (size_t)r0 * DHEAD + (l & 3) * 2;
        float* or8 = or0 + 8 * DHEAD;
#pragma unroll
        for (int nb = 0; nb < 8; ++nb) {
            *(float2*)(or0 + nb * 8) = make_float2(oacc[nb][0] * inv0, oacc[nb][1] * inv0);
            *(float2*)(or8 + nb * 8) = make_float2(oacc[nb][2] * inv1, oacc[nb][3] * inv1);
        }
    }
    __syncthreads();

    // ============================ PASS 2: normalized attention ============================
    issue_k2(0);

    float* ab0 = Ag + (size_t)r0 * SLEN + (l & 3) * 2;

    for (int kt = 0; kt < NKT; ++kt) {

        asm volatile("cp.async.wait_group 0;" ::: "memory");
        __syncthreads();
        convert_k();
        __syncthreads();
        issue_k2(kt + 1);

        // ---- S recompute ----
        float sacc[8][4];
#pragma unroll
        for (int nb = 0; nb < 8; ++nb) { sacc[nb][0]=0.f; sacc[nb][1]=0.f; sacc[nb][2]=0.f; sacc[nb][3]=0.f; }
        const uint32_t aKH = smb + OFF_KH + laneH;
#pragma unroll
        for (int j = 0; j < 4; ++j) {
#pragma unroll
            for (int nb = 0; nb < 8; ++nb) {
                uint32_t b0, b1;
                lds64(b0, b1, aKH + nb * (8 * PH) + j * 32);
                mma_f16(sacc[nb], qa[j], b0, b1);
            }
        }

        // ---- exp * inv, write normalized attention once ----
        uint64_t bits0, bits1;
        {
            uint2 b0v = *(const uint2*)(BMw + rl0 * BM_STRIDE + kt * 2);
            uint2 b1v = *(const uint2*)(BMw + (rl0 + 8) * BM_STRIDE + kt * 2);
            bits0 = ((uint64_t)b0v.y << 32 | b0v.x) >> j0;
            bits1 = ((uint64_t)b1v.y << 32 | b1v.x) >> j0;
        }
        float* ar0 = ab0 + kt * TK;
        float* ar8 = ar0 + 8 * SLEN;
#pragma unroll
        for (int nb = 0; nb < 8; ++nb) {
            const uint32_t s0 = (uint32_t)(bits0 >> (nb * 8));
            const uint32_t s1 = (uint32_t)(bits1 >> (nb * 8));
            float p0 = (s0 & 1) ? __expf(sacc[nb][0] * 0.125f) * inv0 : 0.f;
            float p1 = (s0 & 2) ? __expf(sacc[nb][1] * 0.125f) * inv0 : 0.f;
            float p2 = (s1 & 1) ? __expf(sacc[nb][2] * 0.125f) * inv1 : 0.f;
            float p3 = (s1 & 2) ? __expf(sacc[nb][3] * 0.125f) * inv1 : 0.f;
            *(float2*)(ar0 + nb * 8) = make_float2(p0, p1);
            *(float2*)(ar8 + nb * 8) = make_float2(p2, p3);
        }
    }
}

extern "C" void kernel_launch(void* const* d_in, const int* in_sizes, int n_in,
                              void* d_out, int out_size)
{
    const float* Q    = (const float*)d_in[0];
    const float* K    = (const float*)d_in[1];
    const float* V    = (const float*)d_in[2];
    const int*   mask = (const int*)d_in[3];
    (void)in_sizes; (void)n_in; (void)out_size;

    float* out  = (float*)d_out;
    float* attn = out + OUT_ELEMS;

    static int configured = 0;
    if (!configured) {
        cudaFuncSetAttribute(sdpa_f16_kernel,
                             cudaFuncAttributeMaxDynamicSharedMemorySize, SMEM_BYTES);
        configured = 1;
    }

    dim3 grid(SLEN / TQ, BHN);   // (16, 64)
    sdpa_f16_kernel<<<grid, NTHREADS, SMEM_BYTES>>>(Q, K, V, mask, out, attn);
}

// round 17
// speedup vs baseline: 1.3225x; 1.0033x over previous
#include <cuda_runtime.h>
#include <cuda_fp16.h>
#include <cstdint>

#define SLEN    2048
#define DHEAD   64
#define BHN     64
#define TQ      128
#define TK      64
#define NTHREADS 256
#define NKT     (SLEN / TK)
#define OUT_ELEMS ((size_t)BHN * SLEN * DHEAD)   // 8,388,608

#define PS      272                     // fp32 stage pitch (bytes per 64-f32 row)
#define PH      160                     // fp16 tile pitch (128 B data + 32 pad)

// ---- dynamic smem layout (bytes) ----
#define OFF_KS  0
#define OFF_VS  17408
#define OFF_KH  34816
#define OFF_VT  45056
#define OFF_BM  55296                   // 128 rows x 68 words = 34816
#define OFF_RS  90112                   // 128 floats
#define SMEM_BYTES 90624                // -> 2 CTAs/SM
#define BM_STRIDE 68

#define EXC 0.18033688f                 // log2(e) / 8

static __device__ __forceinline__ uint32_t smem_u32(const void* p) {
    uint32_t a;
    asm("{ .reg .u64 t; cvta.to.shared.u64 t, %1; cvt.u32.u64 %0, t; }" : "=r"(a) : "l"(p));
    return a;
}
static __device__ __forceinline__ void cp16(uint32_t sm, const void* g) {
    asm volatile("cp.async.cg.shared.global [%0], [%1], 16;" :: "r"(sm), "l"(g));
}
static __device__ __forceinline__ float ex2(float x) {
    float r;
    asm("ex2.approx.f32 %0, %1;" : "=f"(r) : "f"(x));
    return r;
}
static __device__ __forceinline__ uint32_t h2pack(float lo, float hi) {
    __half2 h = __floats2half2_rn(lo, hi);
    return *(uint32_t*)&h;
}
static __device__ __forceinline__ void mma_f16(float* c, const uint32_t* a,
                                               uint32_t b0, uint32_t b1) {
    asm volatile("mma.sync.aligned.m16n8k16.row.col.f32.f16.f16.f32 "
                 "{%0,%1,%2,%3}, {%4,%5,%6,%7}, {%8,%9}, {%0,%1,%2,%3};"
                 : "+f"(c[0]), "+f"(c[1]), "+f"(c[2]), "+f"(c[3])
                 : "r"(a[0]), "r"(a[1]), "r"(a[2]), "r"(a[3]), "r"(b0), "r"(b1));
}
static __device__ __forceinline__ void lds64(uint32_t& a, uint32_t& b, uint32_t addr) {
    asm volatile("ld.shared.v2.b32 {%0,%1}, [%2];" : "=r"(a), "=r"(b) : "r"(addr));
}

__global__ void __launch_bounds__(NTHREADS, 2)
sdpa_f16_kernel(const float* __restrict__ Qg_all,
                const float* __restrict__ Kg_all,
                const float* __restrict__ Vg_all,
                const int*   __restrict__ Mg_all,
                float* __restrict__ Og_all,
                float* __restrict__ Ag_all)
{
    extern __shared__ uint8_t smem[];
    const uint32_t smb = smem_u32(smem);
    uint32_t* BMw = (uint32_t*)(smem + OFF_BM);
    float* rowsum = (float*)(smem + OFF_RS);

    const int tid = threadIdx.x;
    const int w   = tid >> 5;
    const int l   = tid & 31;
    const int bh  = blockIdx.y;
    const int q0  = blockIdx.x * TQ;

    const float* Qg = Qg_all + (size_t)bh * SLEN * DHEAD;
    const float* Kg = Kg_all + (size_t)bh * SLEN * DHEAD;
    const float* Vg = Vg_all + (size_t)bh * SLEN * DHEAD;
    const int*   Mg = Mg_all + (size_t)bh * SLEN * SLEN;
    float*       Og = Og_all + (size_t)bh * SLEN * DHEAD;
    float*       Ag = Ag_all + (size_t)bh * SLEN * SLEN;

    // one cp.async group per tile: K (+V in pass 1) raw fp32 into stages
    auto issue_kv = [&](int kt) {
        if (kt < NKT) {
            const float* Kt = Kg + (size_t)kt * TK * DHEAD;
            const float* Vt = Vg + (size_t)kt * TK * DHEAD;
#pragma unroll
            for (int j = 0; j < 4; ++j) {
                const int idx = tid + j * NTHREADS;      // 0..1023
                const int row = idx >> 4, ch = idx & 15;
                cp16(smb + OFF_KS + row * PS + ch * 16, Kt + row * DHEAD + ch * 4);
                cp16(smb + OFF_VS + row * PS + ch * 16, Vt + row * DHEAD + ch * 4);
            }
        }
        asm volatile("cp.async.commit_group;" ::: "memory");
    };
    auto issue_k2 = [&](int kt) {
        if (kt < NKT) {
            const float* Kt = Kg + (size_t)kt * TK * DHEAD;
#pragma unroll
            for (int j = 0; j < 4; ++j) {
                const int idx = tid + j * NTHREADS;
                const int row = idx >> 4, ch = idx & 15;
                cp16(smb + OFF_KS + row * PS + ch * 16, Kt + row * DHEAD + ch * 4);
            }
        }
        asm volatile("cp.async.commit_group;" ::: "memory");
    };
    // KS fp32 -> KH fp16 (natural d order)
    auto convert_k = [&]() {
#pragma unroll
        for (int j = 0; j < 4; ++j) {
            const int idx = tid + j * NTHREADS;
            const int row = idx >> 4, dc = idx & 15;
            float4 v = *(const float4*)(smem + OFF_KS + row * PS + dc * 16);
            uint2 h;
            h.x = h2pack(v.x, v.y);
            h.y = h2pack(v.z, v.w);
            *(uint2*)(smem + OFF_KH + row * PH + dc * 8) = h;
        }
    };
    // VS [k][d] fp32 -> VT [d][pos(k)] fp16, pos = slot permutation for k16 MMA
    auto convert_v = [&]() {
#pragma unroll
        for (int j = 0; j < 4; ++j) {
            const int idx = tid + j * NTHREADS;
            const int k = idx & 63, dc = idx >> 6;       // dc 0..15 -> d = 4dc..4dc+3
            float4 v = *(const float4*)(smem + OFF_VS + k * PS + dc * 16);
            const int q = k & 15, g = k >> 4;
            const int pos = g * 16 + ((q & 6) << 1) + ((q >> 2) & 2) + (q & 1);
            __half h0 = __float2half_rn(v.x);
            __half h1 = __float2half_rn(v.y);
            __half h2 = __float2half_rn(v.z);
            __half h3 = __float2half_rn(v.w);
            uint8_t* base = smem + OFF_VT + pos * 2;
            *(__half*)(base + (dc * 4 + 0) * PH) = h0;
            *(__half*)(base + (dc * 4 + 1) * PH) = h1;
            *(__half*)(base + (dc * 4 + 2) * PH) = h2;
            *(__half*)(base + (dc * 4 + 3) * PH) = h3;
        }
    };

    // prologue
    issue_kv(0);

    // ================= bit-packed mask: 128 rows x 2048 bits =================
    for (int base = 0; base < 8192; base += 64) {
        const int w0idx = base + w * 8;
        int vals[8];
#pragma unroll
        for (int j = 0; j < 8; ++j) {
            const int widx = w0idx + j;
            vals[j] = Mg[(size_t)(q0 + (widx >> 6)) * SLEN + (widx & 63) * 32 + l];
        }
#pragma unroll
        for (int j = 0; j < 8; ++j) {
            const unsigned bal = __ballot_sync(0xffffffffu, vals[j] != 0);
            const int widx = w0idx + j;
            if (l == 0) BMw[(widx >> 6) * BM_STRIDE + (widx & 63)] = bal;
        }
    }

    // ---- Q A-fragments (fp16, m16n8k16 layout; d0 = 16j + 4(l&3)) ----
    const int rl0 = w * 16 + (l >> 2);
    const int r0  = q0 + rl0;
    uint32_t qa[4][4];
    {
        const float* Qr0 = Qg + (size_t)r0 * DHEAD;
        const float* Qr8 = Qr0 + 8 * DHEAD;
#pragma unroll
        for (int j = 0; j < 4; ++j) {
            const int d0 = j * 16 + (l & 3) * 4;
            float4 a = *(const float4*)(Qr0 + d0);
            float4 b = *(const float4*)(Qr8 + d0);
            qa[j][0] = h2pack(a.x, a.y);
            qa[j][1] = h2pack(b.x, b.y);
            qa[j][2] = h2pack(a.z, a.w);
            qa[j][3] = h2pack(b.z, b.w);
        }
    }

    // per-lane B-frag base offset (same formula for KH and VT)
    const uint32_t laneH = (uint32_t)((l >> 2) * PH + (l & 3) * 8);
    const int j0 = (l & 3) * 2;

    float oacc[8][4];
#pragma unroll
    for (int nb = 0; nb < 8; ++nb) { oacc[nb][0]=0.f; oacc[nb][1]=0.f; oacc[nb][2]=0.f; oacc[nb][3]=0.f; }
    float rs0 = 0.f, rs1 = 0.f;

    // ============================ PASS 1: rowsums + O ============================
    for (int kt = 0; kt < NKT; ++kt) {

        asm volatile("cp.async.wait_group 0;" ::: "memory");   // stages = tile kt
        __syncthreads();                                       // all warps done with kt-1 tiles

        convert_v();
        convert_k();
        __syncthreads();

        issue_kv(kt + 1);      // stages free; overlap with compute

        // ---- S = Q K^T (fp16 k16: 32 LDS.64 + 32 MMA) ----
        float sacc[8][4];
#pragma unroll
        for (int nb = 0; nb < 8; ++nb) { sacc[nb][0]=0.f; sacc[nb][1]=0.f; sacc[nb][2]=0.f; sacc[nb][3]=0.f; }
        const uint32_t aKH = smb + OFF_KH + laneH;
#pragma unroll
        for (int j = 0; j < 4; ++j) {
#pragma unroll
            for (int nb = 0; nb < 8; ++nb) {
                uint32_t b0, b1;
                lds64(b0, b1, aKH + nb * (8 * PH) + j * 32);
                mma_f16(sacc[nb], qa[j], b0, b1);
            }
        }

        // ---- mask bits, exp (ex2-folded), rowsum, P halves ----
        uint64_t bits0, bits1;
        {
            uint2 b0v = *(const uint2*)(BMw + rl0 * BM_STRIDE + kt * 2);
            uint2 b1v = *(const uint2*)(BMw + (rl0 + 8) * BM_STRIDE + kt * 2);
            bits0 = ((uint64_t)b0v.y << 32 | b0v.x) >> j0;
            bits1 = ((uint64_t)b1v.y << 32 | b1v.x) >> j0;
        }
        uint32_t phx[8], phy[8];
#pragma unroll
        for (int nb = 0; nb < 8; ++nb) {
            const uint32_t s0 = (uint32_t)(bits0 >> (nb * 8));
            const uint32_t s1 = (uint32_t)(bits1 >> (nb * 8));
            float p0 = (s0 & 1) ? ex2(sacc[nb][0] * EXC) : 0.f;
            float p1 = (s0 & 2) ? ex2(sacc[nb][1] * EXC) : 0.f;
            float p2 = (s1 & 1) ? ex2(sacc[nb][2] * EXC) : 0.f;
            float p3 = (s1 & 2) ? ex2(sacc[nb][3] * EXC) : 0.f;
            rs0 += p0 + p1;
            rs1 += p2 + p3;
            phx[nb] = h2pack(p0, p1);
            phy[nb] = h2pack(p2, p3);
        }

        // ---- O += P V (VT permuted; A-frag = {phx[2j], phy[2j], phx[2j+1], phy[2j+1]}) ----
        const uint32_t aVT = smb + OFF_VT + laneH;
#pragma unroll
        for (int j = 0; j < 4; ++j) {
            uint32_t A[4] = {phx[2 * j], phy[2 * j], phx[2 * j + 1], phy[2 * j + 1]};
#pragma unroll
            for (int nb = 0; nb < 8; ++nb) {
                uint32_t b0, b1;
                lds64(b0, b1, aVT + nb * (8 * PH) + j * 32);
                mma_f16(oacc[nb], A, b0, b1);
            }
        }
    }
    asm volatile("cp.async.wait_group 0;" ::: "memory");   // drain empty tail group

    // ---- row sums: reduce 4 lanes per row, invert ----
    rs0 += __shfl_xor_sync(0xffffffffu, rs0, 1);
    rs0 += __shfl_xor_sync(0xffffffffu, rs0, 2);
    rs1 += __shfl_xor_sync(0xffffffffu, rs1, 1);
    rs1 += __shfl_xor_sync(0xffffffffu, rs1, 2);
    if ((l & 3) == 0) {
        rowsum[rl0]     = rs0;
        rowsum[rl0 + 8] = rs1;
    }
    __syncthreads();
    if (tid < TQ) rowsum[tid] = 1.0f / rowsum[tid];
    __syncthreads();

    const float inv0 = rowsum[rl0];
    const float inv1 = rowsum[rl0 + 8];

    // ---- write normalized O ----
    {
        float* or0 = Og + (size_t)r0 * DHEAD + (l & 3) * 2;
        float* or8 = or0 + 8 * DHEAD;
#pragma unroll
        for (int nb = 0; nb < 8; ++nb) {
            *(float2*)(or0 + nb * 8) = make_float2(oacc[nb][0] * inv0, oacc[nb][1] * inv0);
            *(float2*)(or8 + nb * 8) = make_float2(oacc[nb][2] * inv1, oacc[nb][3] * inv1);
        }
    }
    __syncthreads();

    // ============================ PASS 2: normalized attention ============================
    issue_k2(0);

    // fold normalization into the exponent: p*inv = ex2(s*EXC + log2(inv))
    const float linv0 = __log2f(inv0);
    const float linv1 = __log2f(inv1);

    float* ab0 = Ag + (size_t)r0 * SLEN + (l & 3) * 2;

    for (int kt = 0; kt < NKT; ++kt) {

        asm volatile("cp.async.wait_group 0;" ::: "memory");
        __syncthreads();
        convert_k();
        __syncthreads();
        issue_k2(kt + 1);

        // ---- S recompute ----
        float sacc[8][4];
#pragma unroll
        for (int nb = 0; nb < 8; ++nb) { sacc[nb][0]=0.f; sacc[nb][1]=0.f; sacc[nb][2]=0.f; sacc[nb][3]=0.f; }
        const uint32_t aKH = smb + OFF_KH + laneH;
#pragma unroll
        for (int j = 0; j < 4; ++j) {
#pragma unroll
            for (int nb = 0; nb < 8; ++nb) {
                uint32_t b0, b1;
                lds64(b0, b1, aKH + nb * (8 * PH) + j * 32);
                mma_f16(sacc[nb], qa[j], b0, b1);
            }
        }

        // ---- ex2(fma) with folded normalization, write attention once ----
        uint64_t bits0, bits1;
        {
            uint2 b0v = *(const uint2*)(BMw + rl0 * BM_STRIDE + kt * 2);
            uint2 b1v = *(const uint2*)(BMw + (rl0 + 8) * BM_STRIDE + kt * 2);
            bits0 = ((uint64_t)b0v.y << 32 | b0v.x) >> j0;
            bits1 = ((uint64_t)b1v.y << 32 | b1v.x) >> j0;
        }
        float* ar0 = ab0 + kt * TK;
        float* ar8 = ar0 + 8 * SLEN;
#pragma unroll
        for (int nb = 0; nb < 8; ++nb) {
            const uint32_t s0 = (uint32_t)(bits0 >> (nb * 8));
            const uint32_t s1 = (uint32_t)(bits1 >> (nb * 8));
            float p0 = (s0 & 1) ? ex2(fmaf(sacc[nb][0], EXC, linv0)) : 0.f;
            float p1 = (s0 & 2) ? ex2(fmaf(sacc[nb][1], EXC, linv0)) : 0.f;
            float p2 = (s1 & 1) ? ex2(fmaf(sacc[nb][2], EXC, linv1)) : 0.f;
            float p3 = (s1 & 2) ? ex2(fmaf(sacc[nb][3], EXC, linv1)) : 0.f;
            *(float2*)(ar0 + nb * 8) = make_float2(p0, p1);
            *(float2*)(ar8 + nb * 8) = make_float2(p2, p3);
        }
    }
}

extern "C" void kernel_launch(void* const* d_in, const int* in_sizes, int n_in,
                              void* d_out, int out_size)
{
    const float* Q    = (const float*)d_in[0];
    const float* K    = (const float*)d_in[1];
    const float* V    = (const float*)d_in[2];
    const int*   mask = (const int*)d_in[3];
    (void)in_sizes; (void)n_in; (void)out_size;

    float* out  = (float*)d_out;
    float* attn = out + OUT_ELEMS;

    static int configured = 0;
    if (!configured) {
        cudaFuncSetAttribute(sdpa_f16_kernel,
                             cudaFuncAttributeMaxDynamicSharedMemorySize, SMEM_BYTES);
        configured = 1;
    }

    dim3 grid(SLEN / TQ, BHN);   // (16, 64)
    sdpa_f16_kernel<<<grid, NTHREADS, SMEM_BYTES>>>(Q, K, V, mask, out, attn);
}